// round 3
// baseline (speedup 1.0000x reference)
#include <cuda_runtime.h>
#include <cuda_bf16.h>
#include <cstdint>

// GraphSage: out = relu( [self | mean(neigh)] @ W ),  B=50000, D=128, H=128, K=256.
// fp32 emulated via bf16x3 on the tensor pipe (HMMA mma.sync — compiles for
// compute_103 baseline, unlike tcgen05 which needs the 'a' target):
//   x = hi + lo (bf16);  x*w ~= Ahi*Whi + Ahi*Wlo + Alo*Whi   (err ~2^-16)
//
// Persistent CTAs (<=148), 512 threads, TILE_M=128.
// Per tile: phase0 gathers self feats into A smem (k 0..127), phase1 gathers
// mean-neighbor feats (k 128..255); each phase runs 8 k-steps of
// mma.sync.m16n8k16 with A via ldmatrix.x4 and W via ldmatrix.x4.trans
// (W stays in natural [k][h] layout -> coalesced staging, no transpose pass).

#define NTHREADS 512
#define TILE_M   128
#define H_DIM    128
#define A_STRIDE 136   // 128 k + 8 pad -> 272B rows = 17 chunks, ldmatrix conflict-free
#define W_STRIDE 136   // 128 h + 8 pad

#define SM_AHI 0
#define SM_ALO (SM_AHI + TILE_M * A_STRIDE * 2)          // 34816
#define SM_WHI (SM_ALO + TILE_M * A_STRIDE * 2)          // 69632
#define SM_WLO (SM_WHI + 256 * W_STRIDE * 2)             // 139264
#define SM_TOTAL (SM_WLO + 256 * W_STRIDE * 2)           // 208896

__device__ __forceinline__ uint32_t s2u(const void* p) {
    uint32_t a;
    asm("{ .reg .u64 t; cvta.to.shared.u64 t, %1; cvt.u32.u64 %0, t; }" : "=r"(a) : "l"(p));
    return a;
}

__device__ __forceinline__ void ldsm_x4(uint32_t* r, uint32_t addr) {
    asm volatile("ldmatrix.sync.aligned.m8n8.x4.shared.b16 {%0,%1,%2,%3}, [%4];"
        : "=r"(r[0]), "=r"(r[1]), "=r"(r[2]), "=r"(r[3]) : "r"(addr));
}
__device__ __forceinline__ void ldsm_x4t(uint32_t* r, uint32_t addr) {
    asm volatile("ldmatrix.sync.aligned.m8n8.x4.trans.shared.b16 {%0,%1,%2,%3}, [%4];"
        : "=r"(r[0]), "=r"(r[1]), "=r"(r[2]), "=r"(r[3]) : "r"(addr));
}
__device__ __forceinline__ void mma_bf16(float* c, const uint32_t* a, const uint32_t* b) {
    asm volatile("mma.sync.aligned.m16n8k16.row.col.f32.bf16.bf16.f32 "
        "{%0,%1,%2,%3}, {%4,%5,%6,%7}, {%8,%9}, {%0,%1,%2,%3};"
        : "+f"(c[0]), "+f"(c[1]), "+f"(c[2]), "+f"(c[3])
        : "r"(a[0]), "r"(a[1]), "r"(a[2]), "r"(a[3]), "r"(b[0]), "r"(b[1]));
}

// write 2 consecutive k-values of row r as bf16 hi/lo pairs
__device__ __forceinline__ void writeA(char* sm, int r, int k, float x0, float x1) {
    __nv_bfloat16 h0 = __float2bfloat16_rn(x0);
    __nv_bfloat16 h1 = __float2bfloat16_rn(x1);
    float r0 = x0 - __bfloat162float(h0);
    float r1 = x1 - __bfloat162float(h1);
    uint32_t hi = (uint32_t)__bfloat16_as_ushort(h0) |
                  ((uint32_t)__bfloat16_as_ushort(h1) << 16);
    uint32_t lo = (uint32_t)__bfloat16_as_ushort(__float2bfloat16_rn(r0)) |
                  ((uint32_t)__bfloat16_as_ushort(__float2bfloat16_rn(r1)) << 16);
    const uint32_t o = (uint32_t)(r * A_STRIDE + k) * 2;
    *(uint32_t*)(sm + SM_AHI + o) = hi;
    *(uint32_t*)(sm + SM_ALO + o) = lo;
}

__device__ __forceinline__ uint32_t pack_hi2(float a, float b) {
    return (uint32_t)__bfloat16_as_ushort(__float2bfloat16_rn(a)) |
           ((uint32_t)__bfloat16_as_ushort(__float2bfloat16_rn(b)) << 16);
}

__global__ __launch_bounds__(NTHREADS, 1)
void sage_hmma_kernel(const int* __restrict__ nodes,
                      const int* __restrict__ neigh,
                      const float* __restrict__ feat,
                      const float* __restrict__ W,
                      float* __restrict__ out,
                      int Bn, int nTiles)
{
    extern __shared__ char sm[];
    const uint32_t smb = s2u(sm);
    const int t = threadIdx.x;
    const int wid = t >> 5;
    const int lane = t & 31;

    // ---- stage W as bf16 hi/lo, natural [k][h] layout, coalesced ----
    {
        const float4* w4 = (const float4*)W;   // 8192 float4
        #pragma unroll
        for (int i = 0; i < 16; ++i) {
            const int flat = t + i * NTHREADS;
            float4 v = w4[flat];
            const int k = flat >> 5;            // 32 float4 per k-row
            const int h = (flat & 31) * 4;
            const uint32_t o = (uint32_t)(k * W_STRIDE + h) * 2;
            uint32_t hi0 = pack_hi2(v.x, v.y);
            uint32_t hi1 = pack_hi2(v.z, v.w);
            float rx = v.x - __bfloat162float(__float2bfloat16_rn(v.x));
            float ry = v.y - __bfloat162float(__float2bfloat16_rn(v.y));
            float rz = v.z - __bfloat162float(__float2bfloat16_rn(v.z));
            float rw = v.w - __bfloat162float(__float2bfloat16_rn(v.w));
            uint32_t lo0 = pack_hi2(rx, ry);
            uint32_t lo1 = pack_hi2(rz, rw);
            *(uint2*)(sm + SM_WHI + o) = make_uint2(hi0, hi1);
            *(uint2*)(sm + SM_WLO + o) = make_uint2(lo0, lo1);
        }
    }

    const int wm = wid >> 1;          // 0..7 -> m-tile base wm*16
    const int wn = wid & 1;           // 0..1 -> n-tile base wn*64
    const int m0 = wm * 16;
    const int n0 = wn * 64;

    // ldmatrix lane addresses (byte offsets into smem)
    const int lA_row = m0 + (lane & 15);
    const int lA_kof = (lane >> 4) * 8;
    const int lB_k   = (lane & 15);
    const int lB_hof = n0 + ((lane >> 4) * 8);

    const int gr = t >> 2;            // gather row 0..127
    const int gq = t & 3;             // dim quarter (32 dims)
    const float4* f4 = (const float4*)feat;

    for (int tile = blockIdx.x; tile < nTiles; tile += gridDim.x) {
        const int rowBase = tile * TILE_M;
        const int gb = rowBase + gr;

        float acc[8][4];
        #pragma unroll
        for (int i = 0; i < 8; ++i)
            #pragma unroll
            for (int j = 0; j < 4; ++j) acc[i][j] = 0.f;

        __syncthreads();   // A buffer free (prev tile fully consumed)

        // ---------- gather self -> A (concat k = 0..127) ----------
        if (gb < Bn) {
            const int node = nodes[gb];
            const float4* srow = f4 + (size_t)node * 32 + gq * 8;
            #pragma unroll
            for (int j = 0; j < 8; ++j) {
                float4 v = srow[j];
                const int k = gq * 32 + j * 4;
                writeA(sm, gr, k, v.x, v.y);
                writeA(sm, gr, k + 2, v.z, v.w);
            }
        }
        __syncthreads();

        // ---------- phase 0 MMA: W k-rows 0..127 ----------
        #pragma unroll
        for (int ks = 0; ks < 8; ++ks) {
            const int k0 = ks * 16;
            uint32_t aHi[4], aLo[4];
            const uint32_t aoff = (uint32_t)(lA_row * A_STRIDE + k0 + lA_kof) * 2;
            ldsm_x4(aHi, smb + SM_AHI + aoff);
            ldsm_x4(aLo, smb + SM_ALO + aoff);
            #pragma unroll
            for (int nb = 0; nb < 4; ++nb) {
                uint32_t bHi[4], bLo[4];
                const uint32_t boff =
                    (uint32_t)((k0 + lB_k) * W_STRIDE + lB_hof + nb * 16) * 2;
                ldsm_x4t(bHi, smb + SM_WHI + boff);
                ldsm_x4t(bLo, smb + SM_WLO + boff);
                mma_bf16(acc[nb * 2 + 0], aHi, bHi + 0);
                mma_bf16(acc[nb * 2 + 1], aHi, bHi + 2);
                mma_bf16(acc[nb * 2 + 0], aHi, bLo + 0);
                mma_bf16(acc[nb * 2 + 1], aHi, bLo + 2);
                mma_bf16(acc[nb * 2 + 0], aLo, bHi + 0);
                mma_bf16(acc[nb * 2 + 1], aLo, bHi + 2);
            }
        }
        __syncthreads();   // phase0 A reads done

        // ---------- gather mean(neigh) -> A (concat k = 128..255) ----------
        if (gb < Bn) {
            float4 s[8];
            #pragma unroll
            for (int j = 0; j < 8; ++j) s[j] = make_float4(0.f, 0.f, 0.f, 0.f);
            #pragma unroll
            for (int ns = 0; ns < 10; ++ns) {
                const int ni = neigh[(size_t)gb * 10 + ns];
                const float4* nr = f4 + (size_t)ni * 32 + gq * 8;
                #pragma unroll
                for (int j = 0; j < 8; ++j) {
                    float4 v = nr[j];
                    s[j].x += v.x; s[j].y += v.y; s[j].z += v.z; s[j].w += v.w;
                }
            }
            #pragma unroll
            for (int j = 0; j < 8; ++j) {
                const int k = gq * 32 + j * 4;
                writeA(sm, gr, k, s[j].x * 0.1f, s[j].y * 0.1f);
                writeA(sm, gr, k + 2, s[j].z * 0.1f, s[j].w * 0.1f);
            }
        }
        __syncthreads();

        // ---------- phase 1 MMA: W k-rows 128..255 ----------
        #pragma unroll
        for (int ks = 0; ks < 8; ++ks) {
            const int k0 = ks * 16;
            uint32_t aHi[4], aLo[4];
            const uint32_t aoff = (uint32_t)(lA_row * A_STRIDE + k0 + lA_kof) * 2;
            ldsm_x4(aHi, smb + SM_AHI + aoff);
            ldsm_x4(aLo, smb + SM_ALO + aoff);
            #pragma unroll
            for (int nb = 0; nb < 4; ++nb) {
                uint32_t bHi[4], bLo[4];
                const uint32_t boff =
                    (uint32_t)((128 + k0 + lB_k) * W_STRIDE + lB_hof + nb * 16) * 2;
                ldsm_x4t(bHi, smb + SM_WHI + boff);
                ldsm_x4t(bLo, smb + SM_WLO + boff);
                mma_bf16(acc[nb * 2 + 0], aHi, bHi + 0);
                mma_bf16(acc[nb * 2 + 1], aHi, bHi + 2);
                mma_bf16(acc[nb * 2 + 0], aHi, bLo + 0);
                mma_bf16(acc[nb * 2 + 1], aHi, bLo + 2);
                mma_bf16(acc[nb * 2 + 0], aLo, bHi + 0);
                mma_bf16(acc[nb * 2 + 1], aLo, bHi + 2);
            }
        }

        // ---------- epilogue: relu + stores (regs only, no sync needed) ----------
        {
            const int r0 = rowBase + m0 + (lane >> 2);
            const int r1 = r0 + 8;
            const int c0 = n0 + (lane & 3) * 2;
            #pragma unroll
            for (int nf = 0; nf < 8; ++nf) {
                const int col = c0 + nf * 8;
                if (r0 < Bn) {
                    float2 o;
                    o.x = fmaxf(acc[nf][0], 0.f);
                    o.y = fmaxf(acc[nf][1], 0.f);
                    *(float2*)&out[(size_t)r0 * H_DIM + col] = o;
                }
                if (r1 < Bn) {
                    float2 o;
                    o.x = fmaxf(acc[nf][2], 0.f);
                    o.y = fmaxf(acc[nf][3], 0.f);
                    *(float2*)&out[(size_t)r1 * H_DIM + col] = o;
                }
            }
        }
    }
}

extern "C" void kernel_launch(void* const* d_in, const int* in_sizes, int n_in,
                              void* d_out, int out_size)
{
    const int*   nodes  = (const int*)d_in[0];
    const int*   neigh  = (const int*)d_in[1];
    const float* feat   = (const float*)d_in[2];
    const float* weight = (const float*)d_in[3];
    float*       out    = (float*)d_out;
    const int Bn = in_sizes[0];
    const int nTiles = (Bn + TILE_M - 1) / TILE_M;

    cudaFuncSetAttribute(sage_hmma_kernel,
                         cudaFuncAttributeMaxDynamicSharedMemorySize, SM_TOTAL);

    const int grid = nTiles < 148 ? nTiles : 148;
    sage_hmma_kernel<<<grid, NTHREADS, SM_TOTAL>>>(nodes, neigh, feat, weight, out, Bn, nTiles);
}

// round 5
// speedup vs baseline: 2.4245x; 2.4245x over previous
#include <cuda_runtime.h>
#include <cuda_bf16.h>
#include <cstdint>

// GraphSage: out = relu( [self | mean(neigh)] @ W ),  B=50000, D=128, H=128, K=256.
// bf16x3 emulated fp32 on HMMA (mma.sync m16n8k16), compute_103-safe.
//
// Round-4 restructure:
//  - W pre-converted ONCE (pre-kernel) into mma-B-fragment-ordered bf16 hi/lo
//    in a __device__ global; consumers read it with coalesced LDG.128 (L1 hits,
//    shared across all CTAs). No W smem staging, no ldmatrix for B.
//  - smem = A tile only (17.4 KB) -> TILE_M=32, 128 threads, multiple CTAs/SM
//    so gather and MMA phases of different CTAs overlap.
//  - Gather: one warp per feature row (32 lanes x 16B = 512B contiguous,
//    4 lines/LDG instead of 32). Feature loads via ld.global.cg (bypass L1).

#define NTHREADS 128
#define TILE_M   32
#define H_DIM    128
#define A_STRIDE 136            // elements; 272B rows, ldmatrix conflict-free

#define SM_AHI   0
#define SM_ALO   (TILE_M * A_STRIDE * 2)          // 8704
#define SM_TOTAL (SM_ALO + TILE_M * A_STRIDE * 2) // 17408 B

// W fragments: [kstep 0..15][colblk 0..15][lane 0..31] -> uint4{b0hi,b1hi,b0lo,b1lo}
__device__ uint4 g_wfrag[16 * 16 * 32];

__device__ __forceinline__ uint32_t s2u(const void* p) {
    uint32_t a;
    asm("{ .reg .u64 t; cvta.to.shared.u64 t, %1; cvt.u32.u64 %0, t; }" : "=r"(a) : "l"(p));
    return a;
}
__device__ __forceinline__ void ldsm_x4(uint32_t* r, uint32_t addr) {
    asm volatile("ldmatrix.sync.aligned.m8n8.x4.shared.b16 {%0,%1,%2,%3}, [%4];"
        : "=r"(r[0]), "=r"(r[1]), "=r"(r[2]), "=r"(r[3]) : "r"(addr));
}
__device__ __forceinline__ void mma_bf16(float* c, const uint32_t* a,
                                         uint32_t b0, uint32_t b1) {
    asm volatile("mma.sync.aligned.m16n8k16.row.col.f32.bf16.bf16.f32 "
        "{%0,%1,%2,%3}, {%4,%5,%6,%7}, {%8,%9}, {%0,%1,%2,%3};"
        : "+f"(c[0]), "+f"(c[1]), "+f"(c[2]), "+f"(c[3])
        : "r"(a[0]), "r"(a[1]), "r"(a[2]), "r"(a[3]), "r"(b0), "r"(b1));
}
__device__ __forceinline__ float4 ldcg4(const float4* p) {
    float4 v;
    asm volatile("ld.global.cg.v4.f32 {%0,%1,%2,%3}, [%4];"
        : "=f"(v.x), "=f"(v.y), "=f"(v.z), "=f"(v.w) : "l"(p));
    return v;
}
__device__ __forceinline__ uint32_t pack_hi2(float a, float b) {
    return (uint32_t)__bfloat16_as_ushort(__float2bfloat16_rn(a)) |
           ((uint32_t)__bfloat16_as_ushort(__float2bfloat16_rn(b)) << 16);
}
__device__ __forceinline__ float bf_res(float x) {
    return x - __bfloat162float(__float2bfloat16_rn(x));
}

// ---------------- pre-kernel: W -> fragment-ordered bf16 hi/lo ----------------
// mma m16n8k16 B (col-major k16n8) lane layout:
//   b0 = {B[k0][n], B[k0+1][n]},  b1 = {B[k0+8][n], B[k0+9][n]}
//   with n = lane/4, k0 = (lane%4)*2   (B[k][n] == W[k][n])
__global__ void wfrag_kernel(const float* __restrict__ W) {
    const int tid = blockIdx.x * blockDim.x + threadIdx.x;   // 8192 threads
    const int ks   = tid >> 9;          // 0..15
    const int jblk = (tid >> 5) & 15;   // 0..15
    const int lane = tid & 31;
    const int n  = jblk * 8 + (lane >> 2);
    const int kk = ks * 16 + (lane & 3) * 2;

    const float w0 = W[(kk + 0) * H_DIM + n];
    const float w1 = W[(kk + 1) * H_DIM + n];
    const float w8 = W[(kk + 8) * H_DIM + n];
    const float w9 = W[(kk + 9) * H_DIM + n];

    uint4 f;
    f.x = pack_hi2(w0, w1);                    // b0 hi
    f.y = pack_hi2(w8, w9);                    // b1 hi
    f.z = pack_hi2(bf_res(w0), bf_res(w1));    // b0 lo
    f.w = pack_hi2(bf_res(w8), bf_res(w9));    // b1 lo
    g_wfrag[tid] = f;
}

// ---------------- main kernel ----------------
__global__ __launch_bounds__(NTHREADS, 5)
void sage_main_kernel(const int* __restrict__ nodes,
                      const int* __restrict__ neigh,
                      const float* __restrict__ feat,
                      float* __restrict__ out,
                      int Bn)
{
    __shared__ char sm[SM_TOTAL];
    const uint32_t smb = s2u(sm);
    const int t = threadIdx.x;
    const int wid = t >> 5;          // 0..3
    const int lane = t & 31;
    const int rowBase = blockIdx.x * TILE_M;

    // warp MMA tile: wm in {0,1} -> m0, wn in {0,1} -> n0 (64 cols)
    const int m0 = (wid >> 1) * 16;
    const int n0w = (wid & 1) * 8;   // col-block base (8-col units): 0 or 8

    const float4* f4 = (const float4*)feat;

    float acc[8][4];
    #pragma unroll
    for (int i = 0; i < 8; ++i)
        #pragma unroll
        for (int j = 0; j < 4; ++j) acc[i][j] = 0.f;

    // A-write helper offsets: lane covers float4 idx within a 512B row
    // hi/lo rows: byte (r*A_STRIDE + lane*4)*2 = r*272 + lane*8
    // ldmatrix A address (per k-step k0): row m0+lane%16, col k0+(lane/16)*8
    const uint32_t aAddr = (uint32_t)((m0 + (lane & 15)) * A_STRIDE + (lane >> 4) * 8) * 2;

    // ---------- phase 0: gather self rows (warp per row) ----------
    {
        #pragma unroll
        for (int i = 0; i < 8; ++i) {
            const int r = wid * 8 + i;
            const int b = rowBase + r;
            if (b < Bn) {
                const int node = nodes[b];
                float4 v = ldcg4(f4 + (size_t)node * 32 + lane);
                const uint32_t o = (uint32_t)r * (A_STRIDE * 2) + lane * 8;
                uint2 hi = make_uint2(pack_hi2(v.x, v.y), pack_hi2(v.z, v.w));
                uint2 lo = make_uint2(pack_hi2(bf_res(v.x), bf_res(v.y)),
                                      pack_hi2(bf_res(v.z), bf_res(v.w)));
                *(uint2*)(sm + SM_AHI + o) = hi;
                *(uint2*)(sm + SM_ALO + o) = lo;
            }
        }
    }
    __syncthreads();

    // ---------- MMA phase 0: k-steps 0..7 (self | W rows 0..127) ----------
    #pragma unroll
    for (int ks = 0; ks < 8; ++ks) {
        uint32_t aHi[4], aLo[4];
        const uint32_t ao = aAddr + (uint32_t)(ks * 16) * 2;
        ldsm_x4(aHi, smb + SM_AHI + ao);
        ldsm_x4(aLo, smb + SM_ALO + ao);
        const uint4* fb = &g_wfrag[((ks * 16) + n0w) * 32 + lane];
        #pragma unroll
        for (int j = 0; j < 8; ++j) {
            uint4 f = fb[j * 32];
            mma_bf16(acc[j], aHi, f.x, f.y);
            mma_bf16(acc[j], aHi, f.z, f.w);
            mma_bf16(acc[j], aLo, f.x, f.y);
        }
    }
    __syncthreads();   // all A reads done before overwrite

    // ---------- phase 1: gather mean(neigh) rows ----------
    {
        #pragma unroll
        for (int i = 0; i < 8; ++i) {
            const int r = wid * 8 + i;
            const int b = rowBase + r;
            if (b < Bn) {
                const int* nb = neigh + (size_t)b * 10;
                float4 s = make_float4(0.f, 0.f, 0.f, 0.f);
                #pragma unroll
                for (int ns = 0; ns < 10; ++ns) {
                    float4 v = ldcg4(f4 + (size_t)nb[ns] * 32 + lane);
                    s.x += v.x; s.y += v.y; s.z += v.z; s.w += v.w;
                }
                s.x *= 0.1f; s.y *= 0.1f; s.z *= 0.1f; s.w *= 0.1f;
                const uint32_t o = (uint32_t)r * (A_STRIDE * 2) + lane * 8;
                uint2 hi = make_uint2(pack_hi2(s.x, s.y), pack_hi2(s.z, s.w));
                uint2 lo = make_uint2(pack_hi2(bf_res(s.x), bf_res(s.y)),
                                      pack_hi2(bf_res(s.z), bf_res(s.w)));
                *(uint2*)(sm + SM_AHI + o) = hi;
                *(uint2*)(sm + SM_ALO + o) = lo;
            }
        }
    }
    __syncthreads();

    // ---------- MMA phase 1: k-steps 8..15 (mean | W rows 128..255) ----------
    #pragma unroll
    for (int ks = 0; ks < 8; ++ks) {
        uint32_t aHi[4], aLo[4];
        const uint32_t ao = aAddr + (uint32_t)(ks * 16) * 2;
        ldsm_x4(aHi, smb + SM_AHI + ao);
        ldsm_x4(aLo, smb + SM_ALO + ao);
        const uint4* fb = &g_wfrag[(((8 + ks) * 16) + n0w) * 32 + lane];
        #pragma unroll
        for (int j = 0; j < 8; ++j) {
            uint4 f = fb[j * 32];
            mma_bf16(acc[j], aHi, f.x, f.y);
            mma_bf16(acc[j], aHi, f.z, f.w);
            mma_bf16(acc[j], aLo, f.x, f.y);
        }
    }

    // ---------- epilogue: relu + float2 stores ----------
    {
        const int r0 = rowBase + m0 + (lane >> 2);
        const int r1 = r0 + 8;
        const int c0 = n0w * 8 + (lane & 3) * 2;
        #pragma unroll
        for (int j = 0; j < 8; ++j) {
            const int col = c0 + j * 8;
            if (r0 < Bn) {
                float2 o;
                o.x = fmaxf(acc[j][0], 0.f);
                o.y = fmaxf(acc[j][1], 0.f);
                *(float2*)&out[(size_t)r0 * H_DIM + col] = o;
            }
            if (r1 < Bn) {
                float2 o;
                o.x = fmaxf(acc[j][2], 0.f);
                o.y = fmaxf(acc[j][3], 0.f);
                *(float2*)&out[(size_t)r1 * H_DIM + col] = o;
            }
        }
    }
}

extern "C" void kernel_launch(void* const* d_in, const int* in_sizes, int n_in,
                              void* d_out, int out_size)
{
    const int*   nodes  = (const int*)d_in[0];
    const int*   neigh  = (const int*)d_in[1];
    const float* feat   = (const float*)d_in[2];
    const float* weight = (const float*)d_in[3];
    float*       out    = (float*)d_out;
    const int Bn = in_sizes[0];

    wfrag_kernel<<<64, 128>>>(weight);

    const int grid = (Bn + TILE_M - 1) / TILE_M;
    sage_main_kernel<<<grid, NTHREADS>>>(nodes, neigh, feat, out, Bn);
}

// round 6
// speedup vs baseline: 2.7802x; 1.1467x over previous
#include <cuda_runtime.h>
#include <cuda_bf16.h>
#include <cstdint>

// GraphSage: out = relu( [self | mean(neigh)] @ W ),  B=50000, D=128, H=128, K=256.
// bf16x3 emulated fp32 on HMMA (mma.sync m16n8k16), compute_103-safe.
//
// Round-6: single-barrier CTA. A-tile spans full K=256; each warp gathers
// self + 10 neighbor rows (11 independent 512B loads in flight), ONE
// __syncthreads, then 16 contiguous k-steps of MMA. Gather/MMA phases of
// co-resident CTAs interleave instead of being barrier-chained.

#define NTHREADS 128
#define TILE_M   32
#define H_DIM    128
#define A_STRIDE 264            // elements; 528B rows = 33 chunks, ldmatrix conflict-free

#define SM_AHI   0
#define SM_ALO   (TILE_M * A_STRIDE * 2)          // 16896
#define SM_TOTAL (SM_ALO + TILE_M * A_STRIDE * 2) // 33792 B

// W fragments: [kstep 0..15][colblk 0..15][lane 0..31] -> uint4{b0hi,b1hi,b0lo,b1lo}
__device__ uint4 g_wfrag[16 * 16 * 32];

__device__ __forceinline__ uint32_t s2u(const void* p) {
    uint32_t a;
    asm("{ .reg .u64 t; cvta.to.shared.u64 t, %1; cvt.u32.u64 %0, t; }" : "=r"(a) : "l"(p));
    return a;
}
__device__ __forceinline__ void ldsm_x4(uint32_t* r, uint32_t addr) {
    asm volatile("ldmatrix.sync.aligned.m8n8.x4.shared.b16 {%0,%1,%2,%3}, [%4];"
        : "=r"(r[0]), "=r"(r[1]), "=r"(r[2]), "=r"(r[3]) : "r"(addr));
}
__device__ __forceinline__ void mma_bf16(float* c, const uint32_t* a,
                                         uint32_t b0, uint32_t b1) {
    asm volatile("mma.sync.aligned.m16n8k16.row.col.f32.bf16.bf16.f32 "
        "{%0,%1,%2,%3}, {%4,%5,%6,%7}, {%8,%9}, {%0,%1,%2,%3};"
        : "+f"(c[0]), "+f"(c[1]), "+f"(c[2]), "+f"(c[3])
        : "r"(a[0]), "r"(a[1]), "r"(a[2]), "r"(a[3]), "r"(b0), "r"(b1));
}
__device__ __forceinline__ float4 ldcg4(const float4* p) {
    float4 v;
    asm volatile("ld.global.cg.v4.f32 {%0,%1,%2,%3}, [%4];"
        : "=f"(v.x), "=f"(v.y), "=f"(v.z), "=f"(v.w) : "l"(p));
    return v;
}
__device__ __forceinline__ uint32_t pack_hi2(float a, float b) {
    return (uint32_t)__bfloat16_as_ushort(__float2bfloat16_rn(a)) |
           ((uint32_t)__bfloat16_as_ushort(__float2bfloat16_rn(b)) << 16);
}
__device__ __forceinline__ float bf_res(float x) {
    return x - __bfloat162float(__float2bfloat16_rn(x));
}

// ---------------- pre-kernel: W -> fragment-ordered bf16 hi/lo ----------------
// mma m16n8k16 B (col-major k16n8) lane layout:
//   b0 = {W[k0][n], W[k0+1][n]},  b1 = {W[k0+8][n], W[k0+9][n]}
//   with n = lane/4, k0 = (lane%4)*2
__global__ void wfrag_kernel(const float* __restrict__ W) {
    const int tid = blockIdx.x * blockDim.x + threadIdx.x;   // 8192 threads
    const int ks   = tid >> 9;          // 0..15
    const int jblk = (tid >> 5) & 15;   // 0..15
    const int lane = tid & 31;
    const int n  = jblk * 8 + (lane >> 2);
    const int kk = ks * 16 + (lane & 3) * 2;

    const float w0 = W[(kk + 0) * H_DIM + n];
    const float w1 = W[(kk + 1) * H_DIM + n];
    const float w8 = W[(kk + 8) * H_DIM + n];
    const float w9 = W[(kk + 9) * H_DIM + n];

    uint4 f;
    f.x = pack_hi2(w0, w1);
    f.y = pack_hi2(w8, w9);
    f.z = pack_hi2(bf_res(w0), bf_res(w1));
    f.w = pack_hi2(bf_res(w8), bf_res(w9));
    g_wfrag[tid] = f;
}

// ---------------- main kernel ----------------
__global__ __launch_bounds__(NTHREADS, 5)
void sage_main_kernel(const int* __restrict__ nodes,
                      const int* __restrict__ neigh,
                      const float* __restrict__ feat,
                      float* __restrict__ out,
                      int Bn)
{
    __shared__ char sm[SM_TOTAL];
    const uint32_t smb = s2u(sm);
    const int t = threadIdx.x;
    const int wid = t >> 5;          // 0..3
    const int lane = t & 31;
    const int rowBase = blockIdx.x * TILE_M;

    const int m0 = (wid >> 1) * 16;
    const int n0w = (wid & 1) * 8;   // col-block base (8-col units)

    const float4* f4 = (const float4*)feat;

    // ---------- gather: self + mean(neigh) for 8 rows per warp, one stretch ----------
    #pragma unroll
    for (int i = 0; i < 8; ++i) {
        const int r = wid * 8 + i;
        const int b = rowBase + r;
        if (b < Bn) {
            const int node = nodes[b];
            const int* nb = neigh + (size_t)b * 10;
            int ni[10];
            #pragma unroll
            for (int ns = 0; ns < 10; ++ns) ni[ns] = nb[ns];

            // issue all 11 row loads; compiler batches -> high MLP
            float4 vs = ldcg4(f4 + (size_t)node * 32 + lane);
            float4 v[10];
            #pragma unroll
            for (int ns = 0; ns < 10; ++ns)
                v[ns] = ldcg4(f4 + (size_t)ni[ns] * 32 + lane);

            float4 s = v[0];
            #pragma unroll
            for (int ns = 1; ns < 10; ++ns) {
                s.x += v[ns].x; s.y += v[ns].y; s.z += v[ns].z; s.w += v[ns].w;
            }
            s.x *= 0.1f; s.y *= 0.1f; s.z *= 0.1f; s.w *= 0.1f;

            const uint32_t oS = (uint32_t)r * (A_STRIDE * 2) + lane * 8;         // k = lane*4
            const uint32_t oM = oS + 256;                                        // k = 128 + lane*4
            *(uint2*)(sm + SM_AHI + oS) = make_uint2(pack_hi2(vs.x, vs.y), pack_hi2(vs.z, vs.w));
            *(uint2*)(sm + SM_ALO + oS) = make_uint2(pack_hi2(bf_res(vs.x), bf_res(vs.y)),
                                                     pack_hi2(bf_res(vs.z), bf_res(vs.w)));
            *(uint2*)(sm + SM_AHI + oM) = make_uint2(pack_hi2(s.x, s.y), pack_hi2(s.z, s.w));
            *(uint2*)(sm + SM_ALO + oM) = make_uint2(pack_hi2(bf_res(s.x), bf_res(s.y)),
                                                     pack_hi2(bf_res(s.z), bf_res(s.w)));
        }
    }
    __syncthreads();   // the only barrier in the kernel

    // ---------- MMA: 16 contiguous k-steps over full K=256 ----------
    float acc[8][4];
    #pragma unroll
    for (int i = 0; i < 8; ++i)
        #pragma unroll
        for (int j = 0; j < 4; ++j) acc[i][j] = 0.f;

    const uint32_t aAddr = (uint32_t)((m0 + (lane & 15)) * A_STRIDE + (lane >> 4) * 8) * 2;

    #pragma unroll
    for (int ks = 0; ks < 16; ++ks) {
        uint32_t aHi[4], aLo[4];
        const uint32_t ao = aAddr + (uint32_t)(ks * 16) * 2;
        ldsm_x4(aHi, smb + SM_AHI + ao);
        ldsm_x4(aLo, smb + SM_ALO + ao);
        const uint4* fb = &g_wfrag[((ks * 16) + n0w) * 32 + lane];
        #pragma unroll
        for (int j = 0; j < 8; ++j) {
            uint4 f = fb[j * 32];
            mma_bf16(acc[j], aHi, f.x, f.y);
            mma_bf16(acc[j], aHi, f.z, f.w);
            mma_bf16(acc[j], aLo, f.x, f.y);
        }
    }

    // ---------- epilogue: relu + float2 stores ----------
    {
        const int r0 = rowBase + m0 + (lane >> 2);
        const int r1 = r0 + 8;
        const int c0 = n0w * 8 + (lane & 3) * 2;
        #pragma unroll
        for (int j = 0; j < 8; ++j) {
            const int col = c0 + j * 8;
            if (r0 < Bn) {
                float2 o;
                o.x = fmaxf(acc[j][0], 0.f);
                o.y = fmaxf(acc[j][1], 0.f);
                *(float2*)&out[(size_t)r0 * H_DIM + col] = o;
            }
            if (r1 < Bn) {
                float2 o;
                o.x = fmaxf(acc[j][2], 0.f);
                o.y = fmaxf(acc[j][3], 0.f);
                *(float2*)&out[(size_t)r1 * H_DIM + col] = o;
            }
        }
    }
}

extern "C" void kernel_launch(void* const* d_in, const int* in_sizes, int n_in,
                              void* d_out, int out_size)
{
    const int*   nodes  = (const int*)d_in[0];
    const int*   neigh  = (const int*)d_in[1];
    const float* feat   = (const float*)d_in[2];
    const float* weight = (const float*)d_in[3];
    float*       out    = (float*)d_out;
    const int Bn = in_sizes[0];

    wfrag_kernel<<<64, 128>>>(weight);

    const int grid = (Bn + TILE_M - 1) / TILE_M;
    sage_main_kernel<<<grid, NTHREADS>>>(nodes, neigh, feat, out, Bn);
}

// round 8
// speedup vs baseline: 2.9699x; 1.0682x over previous
#include <cuda_runtime.h>
#include <cuda_bf16.h>
#include <cstdint>

// GraphSage: out = relu( [self | mean(neigh)] @ W ),  B=50000, D=128, H=128, K=256.
// bf16x3 emulated fp32 on HMMA (mma.sync m16n8k16), compute_103-safe.
//
// Round-7: (a) warp tile m32n64 (TILE_M=64) -> each W fragment in registers
// feeds 6 MMAs instead of 3, halving W-fragment L1 traffic per output.
// (b) vectorized index prefetch: warp's 16 rows = 160 contiguous neigh ints
// + 16 node ints, fetched via int4 lane loads into smem scratch, then
// LDS-broadcast -> no serialized uniform-load chain in front of the gathers.

#define NTHREADS 128
#define TILE_M   64
#define H_DIM    128
#define A_STRIDE 264            // elements; 528B rows = 33 chunks, ldmatrix conflict-free

#define SM_AHI   0
#define SM_ALO   (TILE_M * A_STRIDE * 2)            // 33792
#define SM_IDX   (SM_ALO + TILE_M * A_STRIDE * 2)   // 67584
#define SM_TOTAL (SM_IDX + 4 * 176 * 4)             // + idx scratch (4 warps x 176 ints) = 70400

// W fragments: [kstep 0..15][colblk 0..15][lane 0..31] -> uint4{b0hi,b1hi,b0lo,b1lo}
__device__ uint4 g_wfrag[16 * 16 * 32];

__device__ __forceinline__ uint32_t s2u(const void* p) {
    uint32_t a;
    asm("{ .reg .u64 t; cvta.to.shared.u64 t, %1; cvt.u32.u64 %0, t; }" : "=r"(a) : "l"(p));
    return a;
}
__device__ __forceinline__ void ldsm_x4(uint32_t* r, uint32_t addr) {
    asm volatile("ldmatrix.sync.aligned.m8n8.x4.shared.b16 {%0,%1,%2,%3}, [%4];"
        : "=r"(r[0]), "=r"(r[1]), "=r"(r[2]), "=r"(r[3]) : "r"(addr));
}
__device__ __forceinline__ void mma_bf16(float* c, const uint32_t* a,
                                         uint32_t b0, uint32_t b1) {
    asm volatile("mma.sync.aligned.m16n8k16.row.col.f32.bf16.bf16.f32 "
        "{%0,%1,%2,%3}, {%4,%5,%6,%7}, {%8,%9}, {%0,%1,%2,%3};"
        : "+f"(c[0]), "+f"(c[1]), "+f"(c[2]), "+f"(c[3])
        : "r"(a[0]), "r"(a[1]), "r"(a[2]), "r"(a[3]), "r"(b0), "r"(b1));
}
__device__ __forceinline__ float4 ldcg4(const float4* p) {
    float4 v;
    asm volatile("ld.global.cg.v4.f32 {%0,%1,%2,%3}, [%4];"
        : "=f"(v.x), "=f"(v.y), "=f"(v.z), "=f"(v.w) : "l"(p));
    return v;
}
__device__ __forceinline__ uint32_t pack_hi2(float a, float b) {
    return (uint32_t)__bfloat16_as_ushort(__float2bfloat16_rn(a)) |
           ((uint32_t)__bfloat16_as_ushort(__float2bfloat16_rn(b)) << 16);
}
__device__ __forceinline__ float bf_res(float x) {
    return x - __bfloat162float(__float2bfloat16_rn(x));
}

// ---------------- pre-kernel: W -> fragment-ordered bf16 hi/lo ----------------
__global__ void wfrag_kernel(const float* __restrict__ W) {
    const int tid = blockIdx.x * blockDim.x + threadIdx.x;   // 8192 threads
    const int ks   = tid >> 9;
    const int jblk = (tid >> 5) & 15;
    const int lane = tid & 31;
    const int n  = jblk * 8 + (lane >> 2);
    const int kk = ks * 16 + (lane & 3) * 2;

    const float w0 = W[(kk + 0) * H_DIM + n];
    const float w1 = W[(kk + 1) * H_DIM + n];
    const float w8 = W[(kk + 8) * H_DIM + n];
    const float w9 = W[(kk + 9) * H_DIM + n];

    uint4 f;
    f.x = pack_hi2(w0, w1);
    f.y = pack_hi2(w8, w9);
    f.z = pack_hi2(bf_res(w0), bf_res(w1));
    f.w = pack_hi2(bf_res(w8), bf_res(w9));
    g_wfrag[tid] = f;
}

// ---------------- main kernel ----------------
__global__ __launch_bounds__(NTHREADS, 3)
void sage_main_kernel(const int* __restrict__ nodes,
                      const int* __restrict__ neigh,
                      const float* __restrict__ feat,
                      float* __restrict__ out,
                      int Bn)
{
    extern __shared__ char sm[];
    const uint32_t smb = s2u(sm);
    const int t = threadIdx.x;
    const int wid = t >> 5;          // 0..3
    const int lane = t & 31;
    const int rowBase = blockIdx.x * TILE_M;

    const float4* f4 = (const float4*)feat;

    // ---------- index prefetch: warp covers rows wid*16 .. wid*16+15 ----------
    const int rbase = wid * 16;
    const int b0 = rowBase + rbase;
    int* scN = (int*)(sm + SM_IDX) + wid * 176;   // [0..15]=nodes, [16..175]=neigh

    if (b0 + 16 <= Bn) {
        if (lane < 4)
            ((int4*)scN)[lane] = ((const int4*)(nodes + b0))[lane];
        const int4* np = (const int4*)(neigh + (size_t)b0 * 10);
        ((int4*)(scN + 16))[lane] = np[lane];
        if (lane < 8)
            ((int4*)(scN + 16))[32 + lane] = np[32 + lane];
    } else if (b0 < Bn) {
        for (int i = lane; i < 16; i += 32) {
            const int b = b0 + i;
            scN[i] = (b < Bn) ? nodes[b] : 0;
        }
        for (int i = lane; i < 160; i += 32) {
            const int b = b0 + i / 10;
            scN[16 + i] = (b < Bn) ? neigh[(size_t)b * 10 + (i % 10)] : 0;
        }
    }
    __syncwarp();

    // ---------- gather: self + mean(neigh), 16 rows per warp ----------
    #pragma unroll 2
    for (int i = 0; i < 16; ++i) {
        const int b = b0 + i;
        if (b < Bn) {
            const int node = scN[i];
            const int* ni = scN + 16 + i * 10;

            float4 vs = ldcg4(f4 + (size_t)node * 32 + lane);
            float4 v[10];
            #pragma unroll
            for (int ns = 0; ns < 10; ++ns)
                v[ns] = ldcg4(f4 + (size_t)ni[ns] * 32 + lane);

            float4 s = v[0];
            #pragma unroll
            for (int ns = 1; ns < 10; ++ns) {
                s.x += v[ns].x; s.y += v[ns].y; s.z += v[ns].z; s.w += v[ns].w;
            }
            s.x *= 0.1f; s.y *= 0.1f; s.z *= 0.1f; s.w *= 0.1f;

            const int r = rbase + i;
            const uint32_t oS = (uint32_t)r * (A_STRIDE * 2) + lane * 8;  // k = lane*4
            const uint32_t oM = oS + 256;                                 // k = 128+lane*4
            *(uint2*)(sm + SM_AHI + oS) = make_uint2(pack_hi2(vs.x, vs.y), pack_hi2(vs.z, vs.w));
            *(uint2*)(sm + SM_ALO + oS) = make_uint2(pack_hi2(bf_res(vs.x), bf_res(vs.y)),
                                                     pack_hi2(bf_res(vs.z), bf_res(vs.w)));
            *(uint2*)(sm + SM_AHI + oM) = make_uint2(pack_hi2(s.x, s.y), pack_hi2(s.z, s.w));
            *(uint2*)(sm + SM_ALO + oM) = make_uint2(pack_hi2(bf_res(s.x), bf_res(s.y)),
                                                     pack_hi2(bf_res(s.z), bf_res(s.w)));
        }
    }
    __syncthreads();   // the only CTA barrier

    // ---------- MMA: warp tile m32 x n64, 16 k-steps ----------
    const int m0w = (wid >> 1) * 32;
    const int n0w = (wid & 1) * 8;   // col-block base (8-col units)

    float acc0[8][4], acc1[8][4];
    #pragma unroll
    for (int j = 0; j < 8; ++j)
        #pragma unroll
        for (int c = 0; c < 4; ++c) { acc0[j][c] = 0.f; acc1[j][c] = 0.f; }

    const uint32_t aAddr0 = (uint32_t)((m0w + (lane & 15)) * A_STRIDE + (lane >> 4) * 8) * 2;
    const uint32_t aAddr1 = aAddr0 + 16 * A_STRIDE * 2;

    #pragma unroll 4
    for (int ks = 0; ks < 16; ++ks) {
        uint32_t aHi0[4], aLo0[4], aHi1[4], aLo1[4];
        const uint32_t ao = (uint32_t)(ks * 16) * 2;
        ldsm_x4(aHi0, smb + SM_AHI + aAddr0 + ao);
        ldsm_x4(aLo0, smb + SM_ALO + aAddr0 + ao);
        ldsm_x4(aHi1, smb + SM_AHI + aAddr1 + ao);
        ldsm_x4(aLo1, smb + SM_ALO + aAddr1 + ao);
        const uint4* fb = &g_wfrag[((ks * 16) + n0w) * 32 + lane];
        #pragma unroll
        for (int j = 0; j < 8; ++j) {
            uint4 f = fb[j * 32];
            mma_bf16(acc0[j], aHi0, f.x, f.y);
            mma_bf16(acc0[j], aHi0, f.z, f.w);
            mma_bf16(acc0[j], aLo0, f.x, f.y);
            mma_bf16(acc1[j], aHi1, f.x, f.y);
            mma_bf16(acc1[j], aHi1, f.z, f.w);
            mma_bf16(acc1[j], aLo1, f.x, f.y);
        }
    }

    // ---------- epilogue: relu + float2 stores, both m-halves ----------
    #pragma unroll
    for (int h = 0; h < 2; ++h) {
        float (*acc)[4] = h ? acc1 : acc0;
        const int r0 = rowBase + m0w + h * 16 + (lane >> 2);
        const int r1 = r0 + 8;
        const int c0 = n0w * 8 + (lane & 3) * 2;
        #pragma unroll
        for (int j = 0; j < 8; ++j) {
            const int col = c0 + j * 8;
            if (r0 < Bn) {
                float2 o;
                o.x = fmaxf(acc[j][0], 0.f);
                o.y = fmaxf(acc[j][1], 0.f);
                *(float2*)&out[(size_t)r0 * H_DIM + col] = o;
            }
            if (r1 < Bn) {
                float2 o;
                o.x = fmaxf(acc[j][2], 0.f);
                o.y = fmaxf(acc[j][3], 0.f);
                *(float2*)&out[(size_t)r1 * H_DIM + col] = o;
            }
        }
    }
}

extern "C" void kernel_launch(void* const* d_in, const int* in_sizes, int n_in,
                              void* d_out, int out_size)
{
    const int*   nodes  = (const int*)d_in[0];
    const int*   neigh  = (const int*)d_in[1];
    const float* feat   = (const float*)d_in[2];
    const float* weight = (const float*)d_in[3];
    float*       out    = (float*)d_out;
    const int Bn = in_sizes[0];

    wfrag_kernel<<<64, 128>>>(weight);

    cudaFuncSetAttribute(sage_main_kernel,
                         cudaFuncAttributeMaxDynamicSharedMemorySize, SM_TOTAL);
    const int grid = (Bn + TILE_M - 1) / TILE_M;
    sage_main_kernel<<<grid, NTHREADS, SM_TOTAL>>>(nodes, neigh, feat, out, Bn);
}

// round 9
// speedup vs baseline: 3.3431x; 1.1257x over previous
#include <cuda_runtime.h>
#include <cuda_bf16.h>
#include <cstdint>

// GraphSage: out = relu( [self | mean(neigh)] @ W ),  B=50000, D=128, H=128, K=256.
// bf16x3 emulated fp32 on HMMA (mma.sync m16n8k16), compute_103-safe.
//
// Round-8: m32n32 warp tiles (keeps 6 MMAs per W-fragment) + reg cap 128 via
// __launch_bounds__(128,4) -> 4 CTAs/SM (occ ~25%) + two-batch neighbor sums
// to keep gather-phase register pressure low. TILE_M=32, smem 34.5 KB static.

#define NTHREADS 128
#define TILE_M   32
#define H_DIM    128
#define A_STRIDE 264            // elements; 528B rows = 33 chunks, ldmatrix conflict-free

#define SM_AHI   0
#define SM_ALO   (TILE_M * A_STRIDE * 2)            // 16896
#define SM_IDX   (SM_ALO + TILE_M * A_STRIDE * 2)   // 33792
#define SM_TOTAL (SM_IDX + 4 * 96 * 4)              // + idx scratch = 35328 B (static)

// W fragments: [kstep 0..15][colblk 0..15][lane 0..31] -> uint4{b0hi,b1hi,b0lo,b1lo}
__device__ uint4 g_wfrag[16 * 16 * 32];

__device__ __forceinline__ uint32_t s2u(const void* p) {
    uint32_t a;
    asm("{ .reg .u64 t; cvta.to.shared.u64 t, %1; cvt.u32.u64 %0, t; }" : "=r"(a) : "l"(p));
    return a;
}
__device__ __forceinline__ void ldsm_x4(uint32_t* r, uint32_t addr) {
    asm volatile("ldmatrix.sync.aligned.m8n8.x4.shared.b16 {%0,%1,%2,%3}, [%4];"
        : "=r"(r[0]), "=r"(r[1]), "=r"(r[2]), "=r"(r[3]) : "r"(addr));
}
__device__ __forceinline__ void mma_bf16(float* c, const uint32_t* a,
                                         uint32_t b0, uint32_t b1) {
    asm volatile("mma.sync.aligned.m16n8k16.row.col.f32.bf16.bf16.f32 "
        "{%0,%1,%2,%3}, {%4,%5,%6,%7}, {%8,%9}, {%0,%1,%2,%3};"
        : "+f"(c[0]), "+f"(c[1]), "+f"(c[2]), "+f"(c[3])
        : "r"(a[0]), "r"(a[1]), "r"(a[2]), "r"(a[3]), "r"(b0), "r"(b1));
}
__device__ __forceinline__ float4 ldcg4(const float4* p) {
    float4 v;
    asm volatile("ld.global.cg.v4.f32 {%0,%1,%2,%3}, [%4];"
        : "=f"(v.x), "=f"(v.y), "=f"(v.z), "=f"(v.w) : "l"(p));
    return v;
}
__device__ __forceinline__ uint32_t pack_hi2(float a, float b) {
    return (uint32_t)__bfloat16_as_ushort(__float2bfloat16_rn(a)) |
           ((uint32_t)__bfloat16_as_ushort(__float2bfloat16_rn(b)) << 16);
}
__device__ __forceinline__ float bf_res(float x) {
    return x - __bfloat162float(__float2bfloat16_rn(x));
}

// ---------------- pre-kernel: W -> fragment-ordered bf16 hi/lo ----------------
__global__ void wfrag_kernel(const float* __restrict__ W) {
    const int tid = blockIdx.x * blockDim.x + threadIdx.x;   // 8192 threads
    const int ks   = tid >> 9;
    const int jblk = (tid >> 5) & 15;
    const int lane = tid & 31;
    const int n  = jblk * 8 + (lane >> 2);
    const int kk = ks * 16 + (lane & 3) * 2;

    const float w0 = W[(kk + 0) * H_DIM + n];
    const float w1 = W[(kk + 1) * H_DIM + n];
    const float w8 = W[(kk + 8) * H_DIM + n];
    const float w9 = W[(kk + 9) * H_DIM + n];

    uint4 f;
    f.x = pack_hi2(w0, w1);
    f.y = pack_hi2(w8, w9);
    f.z = pack_hi2(bf_res(w0), bf_res(w1));
    f.w = pack_hi2(bf_res(w8), bf_res(w9));
    g_wfrag[tid] = f;
}

// ---------------- main kernel ----------------
__global__ __launch_bounds__(NTHREADS, 4)
void sage_main_kernel(const int* __restrict__ nodes,
                      const int* __restrict__ neigh,
                      const float* __restrict__ feat,
                      float* __restrict__ out,
                      int Bn)
{
    __shared__ char sm[SM_TOTAL];
    const uint32_t smb = s2u(sm);
    const int t = threadIdx.x;
    const int wid = t >> 5;          // 0..3
    const int lane = t & 31;
    const int rowBase = blockIdx.x * TILE_M;

    const float4* f4 = (const float4*)feat;

    // ---------- index prefetch: warp covers rows wid*8 .. wid*8+7 ----------
    const int rbase = wid * 8;
    const int b0 = rowBase + rbase;
    int* scN = (int*)(sm + SM_IDX) + wid * 96;   // [0..7]=nodes, [8..87]=neigh

    if (b0 + 8 <= Bn) {
        if (lane < 2)
            ((int4*)scN)[lane] = ((const int4*)(nodes + b0))[lane];
        if (lane < 20)
            ((int4*)(scN + 8))[lane] = ((const int4*)(neigh + (size_t)b0 * 10))[lane];
    } else if (b0 < Bn) {
        for (int i = lane; i < 8; i += 32) {
            const int b = b0 + i;
            scN[i] = (b < Bn) ? nodes[b] : 0;
        }
        for (int i = lane; i < 80; i += 32) {
            const int b = b0 + i / 10;
            scN[8 + i] = (b < Bn) ? neigh[(size_t)b * 10 + (i % 10)] : 0;
        }
    }
    __syncwarp();

    // ---------- gather: self + mean(neigh), 8 rows per warp ----------
    #pragma unroll
    for (int i = 0; i < 8; ++i) {
        const int b = b0 + i;
        if (b < Bn) {
            const int node = scN[i];
            const int* ni = scN + 8 + i * 10;

            // batch 1: self + first 5 neighbors in flight together
            float4 vs = ldcg4(f4 + (size_t)node * 32 + lane);
            float4 v0 = ldcg4(f4 + (size_t)ni[0] * 32 + lane);
            float4 v1 = ldcg4(f4 + (size_t)ni[1] * 32 + lane);
            float4 v2 = ldcg4(f4 + (size_t)ni[2] * 32 + lane);
            float4 v3 = ldcg4(f4 + (size_t)ni[3] * 32 + lane);
            float4 v4 = ldcg4(f4 + (size_t)ni[4] * 32 + lane);
            float4 s;
            s.x = v0.x + v1.x + v2.x + v3.x + v4.x;
            s.y = v0.y + v1.y + v2.y + v3.y + v4.y;
            s.z = v0.z + v1.z + v2.z + v3.z + v4.z;
            s.w = v0.w + v1.w + v2.w + v3.w + v4.w;
            // batch 2
            v0 = ldcg4(f4 + (size_t)ni[5] * 32 + lane);
            v1 = ldcg4(f4 + (size_t)ni[6] * 32 + lane);
            v2 = ldcg4(f4 + (size_t)ni[7] * 32 + lane);
            v3 = ldcg4(f4 + (size_t)ni[8] * 32 + lane);
            v4 = ldcg4(f4 + (size_t)ni[9] * 32 + lane);
            s.x += v0.x + v1.x + v2.x + v3.x + v4.x;
            s.y += v0.y + v1.y + v2.y + v3.y + v4.y;
            s.z += v0.z + v1.z + v2.z + v3.z + v4.z;
            s.w += v0.w + v1.w + v2.w + v3.w + v4.w;
            s.x *= 0.1f; s.y *= 0.1f; s.z *= 0.1f; s.w *= 0.1f;

            const int r = rbase + i;
            const uint32_t oS = (uint32_t)r * (A_STRIDE * 2) + lane * 8;  // k = lane*4
            const uint32_t oM = oS + 256;                                 // k = 128+lane*4
            *(uint2*)(sm + SM_AHI + oS) = make_uint2(pack_hi2(vs.x, vs.y), pack_hi2(vs.z, vs.w));
            *(uint2*)(sm + SM_ALO + oS) = make_uint2(pack_hi2(bf_res(vs.x), bf_res(vs.y)),
                                                     pack_hi2(bf_res(vs.z), bf_res(vs.w)));
            *(uint2*)(sm + SM_AHI + oM) = make_uint2(pack_hi2(s.x, s.y), pack_hi2(s.z, s.w));
            *(uint2*)(sm + SM_ALO + oM) = make_uint2(pack_hi2(bf_res(s.x), bf_res(s.y)),
                                                     pack_hi2(bf_res(s.z), bf_res(s.w)));
        }
    }
    __syncthreads();   // the only CTA barrier

    // ---------- MMA: warp tile m32 x n32 (4 col-blocks), 16 k-steps ----------
    const int n0w = wid * 4;   // col-block base (8-col units): warp covers cols wid*32..+31

    float acc0[4][4], acc1[4][4];
    #pragma unroll
    for (int j = 0; j < 4; ++j)
        #pragma unroll
        for (int c = 0; c < 4; ++c) { acc0[j][c] = 0.f; acc1[j][c] = 0.f; }

    const uint32_t aAddr0 = (uint32_t)(((lane & 15)) * A_STRIDE + (lane >> 4) * 8) * 2;
    const uint32_t aAddr1 = aAddr0 + 16 * A_STRIDE * 2;

    #pragma unroll 4
    for (int ks = 0; ks < 16; ++ks) {
        uint32_t aHi0[4], aLo0[4], aHi1[4], aLo1[4];
        const uint32_t ao = (uint32_t)(ks * 16) * 2;
        ldsm_x4(aHi0, smb + SM_AHI + aAddr0 + ao);
        ldsm_x4(aLo0, smb + SM_ALO + aAddr0 + ao);
        ldsm_x4(aHi1, smb + SM_AHI + aAddr1 + ao);
        ldsm_x4(aLo1, smb + SM_ALO + aAddr1 + ao);
        const uint4* fb = &g_wfrag[((ks * 16) + n0w) * 32 + lane];
        #pragma unroll
        for (int j = 0; j < 4; ++j) {
            uint4 f = fb[j * 32];
            mma_bf16(acc0[j], aHi0, f.x, f.y);
            mma_bf16(acc0[j], aHi0, f.z, f.w);
            mma_bf16(acc0[j], aLo0, f.x, f.y);
            mma_bf16(acc1[j], aHi1, f.x, f.y);
            mma_bf16(acc1[j], aHi1, f.z, f.w);
            mma_bf16(acc1[j], aLo1, f.x, f.y);
        }
    }

    // ---------- epilogue: relu + float2 stores, both m-halves ----------
    #pragma unroll
    for (int h = 0; h < 2; ++h) {
        float (*acc)[4] = h ? acc1 : acc0;
        const int r0 = rowBase + h * 16 + (lane >> 2);
        const int r1 = r0 + 8;
        const int c0 = wid * 32 + (lane & 3) * 2;
        #pragma unroll
        for (int j = 0; j < 4; ++j) {
            const int col = c0 + j * 8;
            if (r0 < Bn) {
                float2 o;
                o.x = fmaxf(acc[j][0], 0.f);
                o.y = fmaxf(acc[j][1], 0.f);
                *(float2*)&out[(size_t)r0 * H_DIM + col] = o;
            }
            if (r1 < Bn) {
                float2 o;
                o.x = fmaxf(acc[j][2], 0.f);
                o.y = fmaxf(acc[j][3], 0.f);
                *(float2*)&out[(size_t)r1 * H_DIM + col] = o;
            }
        }
    }
}

extern "C" void kernel_launch(void* const* d_in, const int* in_sizes, int n_in,
                              void* d_out, int out_size)
{
    const int*   nodes  = (const int*)d_in[0];
    const int*   neigh  = (const int*)d_in[1];
    const float* feat   = (const float*)d_in[2];
    const float* weight = (const float*)d_in[3];
    float*       out    = (float*)d_out;
    const int Bn = in_sizes[0];

    wfrag_kernel<<<64, 128>>>(weight);

    const int grid = (Bn + TILE_M - 1) / TILE_M;
    sage_main_kernel<<<grid, NTHREADS>>>(nodes, neigh, feat, out, Bn);
}

// round 10
// speedup vs baseline: 3.7454x; 1.1204x over previous
#include <cuda_runtime.h>
#include <cuda_bf16.h>
#include <cstdint>

// GraphSage: out = relu( [self | mean(neigh)] @ W ),  B=50000, D=128, H=128, K=256.
// bf16x3 emulated fp32 on HMMA (mma.sync m16n8k16), compute_103-safe.
//
// Round-9: W-fragment loads software-pipelined 2 ksteps ahead in registers,
// via ld.global.cg (L1 can't hold the 128KB fragment set once 141KB of smem
// is carved out -> every kstep was eating an exposed ~L2-latency stall).
// Everything else = round-8 (m32n32 warp tiles, idx prefetch, bf16x3).

#define NTHREADS 128
#define TILE_M   32
#define H_DIM    128
#define A_STRIDE 264            // elements; 528B rows = 33 chunks, ldmatrix conflict-free

#define SM_AHI   0
#define SM_ALO   (TILE_M * A_STRIDE * 2)            // 16896
#define SM_IDX   (SM_ALO + TILE_M * A_STRIDE * 2)   // 33792
#define SM_TOTAL (SM_IDX + 4 * 96 * 4)              // 35328 B (static)

// W fragments: [kstep 0..15][colblk 0..15][lane 0..31] -> uint4{b0hi,b1hi,b0lo,b1lo}
__device__ uint4 g_wfrag[16 * 16 * 32];

__device__ __forceinline__ uint32_t s2u(const void* p) {
    uint32_t a;
    asm("{ .reg .u64 t; cvta.to.shared.u64 t, %1; cvt.u32.u64 %0, t; }" : "=r"(a) : "l"(p));
    return a;
}
__device__ __forceinline__ void ldsm_x4(uint32_t* r, uint32_t addr) {
    asm volatile("ldmatrix.sync.aligned.m8n8.x4.shared.b16 {%0,%1,%2,%3}, [%4];"
        : "=r"(r[0]), "=r"(r[1]), "=r"(r[2]), "=r"(r[3]) : "r"(addr));
}
__device__ __forceinline__ void mma_bf16(float* c, const uint32_t* a,
                                         uint32_t b0, uint32_t b1) {
    asm volatile("mma.sync.aligned.m16n8k16.row.col.f32.bf16.bf16.f32 "
        "{%0,%1,%2,%3}, {%4,%5,%6,%7}, {%8,%9}, {%0,%1,%2,%3};"
        : "+f"(c[0]), "+f"(c[1]), "+f"(c[2]), "+f"(c[3])
        : "r"(a[0]), "r"(a[1]), "r"(a[2]), "r"(a[3]), "r"(b0), "r"(b1));
}
__device__ __forceinline__ float4 ldcg4(const float4* p) {
    float4 v;
    asm volatile("ld.global.cg.v4.f32 {%0,%1,%2,%3}, [%4];"
        : "=f"(v.x), "=f"(v.y), "=f"(v.z), "=f"(v.w) : "l"(p));
    return v;
}
__device__ __forceinline__ uint4 ldcg4u(const uint4* p) {
    uint4 v;
    asm volatile("ld.global.cg.v4.u32 {%0,%1,%2,%3}, [%4];"
        : "=r"(v.x), "=r"(v.y), "=r"(v.z), "=r"(v.w) : "l"(p));
    return v;
}
__device__ __forceinline__ uint32_t pack_hi2(float a, float b) {
    return (uint32_t)__bfloat16_as_ushort(__float2bfloat16_rn(a)) |
           ((uint32_t)__bfloat16_as_ushort(__float2bfloat16_rn(b)) << 16);
}
__device__ __forceinline__ float bf_res(float x) {
    return x - __bfloat162float(__float2bfloat16_rn(x));
}

// ---------------- pre-kernel: W -> fragment-ordered bf16 hi/lo ----------------
__global__ void wfrag_kernel(const float* __restrict__ W) {
    const int tid = blockIdx.x * blockDim.x + threadIdx.x;   // 8192 threads
    const int ks   = tid >> 9;
    const int jblk = (tid >> 5) & 15;
    const int lane = tid & 31;
    const int n  = jblk * 8 + (lane >> 2);
    const int kk = ks * 16 + (lane & 3) * 2;

    const float w0 = W[(kk + 0) * H_DIM + n];
    const float w1 = W[(kk + 1) * H_DIM + n];
    const float w8 = W[(kk + 8) * H_DIM + n];
    const float w9 = W[(kk + 9) * H_DIM + n];

    uint4 f;
    f.x = pack_hi2(w0, w1);
    f.y = pack_hi2(w8, w9);
    f.z = pack_hi2(bf_res(w0), bf_res(w1));
    f.w = pack_hi2(bf_res(w8), bf_res(w9));
    g_wfrag[tid] = f;
}

// ---------------- main kernel ----------------
__global__ __launch_bounds__(NTHREADS, 4)
void sage_main_kernel(const int* __restrict__ nodes,
                      const int* __restrict__ neigh,
                      const float* __restrict__ feat,
                      float* __restrict__ out,
                      int Bn)
{
    __shared__ char sm[SM_TOTAL];
    const uint32_t smb = s2u(sm);
    const int t = threadIdx.x;
    const int wid = t >> 5;          // 0..3
    const int lane = t & 31;
    const int rowBase = blockIdx.x * TILE_M;

    const float4* f4 = (const float4*)feat;

    // ---------- index prefetch: warp covers rows wid*8 .. wid*8+7 ----------
    const int rbase = wid * 8;
    const int b0 = rowBase + rbase;
    int* scN = (int*)(sm + SM_IDX) + wid * 96;   // [0..7]=nodes, [8..87]=neigh

    if (b0 + 8 <= Bn) {
        if (lane < 2)
            ((int4*)scN)[lane] = ((const int4*)(nodes + b0))[lane];
        if (lane < 20)
            ((int4*)(scN + 8))[lane] = ((const int4*)(neigh + (size_t)b0 * 10))[lane];
    } else if (b0 < Bn) {
        for (int i = lane; i < 8; i += 32) {
            const int b = b0 + i;
            scN[i] = (b < Bn) ? nodes[b] : 0;
        }
        for (int i = lane; i < 80; i += 32) {
            const int b = b0 + i / 10;
            scN[8 + i] = (b < Bn) ? neigh[(size_t)b * 10 + (i % 10)] : 0;
        }
    }
    __syncwarp();

    // ---------- gather: self + mean(neigh), 8 rows per warp ----------
    #pragma unroll
    for (int i = 0; i < 8; ++i) {
        const int b = b0 + i;
        if (b < Bn) {
            const int node = scN[i];
            const int* ni = scN + 8 + i * 10;

            float4 vs = ldcg4(f4 + (size_t)node * 32 + lane);
            float4 v0 = ldcg4(f4 + (size_t)ni[0] * 32 + lane);
            float4 v1 = ldcg4(f4 + (size_t)ni[1] * 32 + lane);
            float4 v2 = ldcg4(f4 + (size_t)ni[2] * 32 + lane);
            float4 v3 = ldcg4(f4 + (size_t)ni[3] * 32 + lane);
            float4 v4 = ldcg4(f4 + (size_t)ni[4] * 32 + lane);
            float4 s;
            s.x = v0.x + v1.x + v2.x + v3.x + v4.x;
            s.y = v0.y + v1.y + v2.y + v3.y + v4.y;
            s.z = v0.z + v1.z + v2.z + v3.z + v4.z;
            s.w = v0.w + v1.w + v2.w + v3.w + v4.w;
            v0 = ldcg4(f4 + (size_t)ni[5] * 32 + lane);
            v1 = ldcg4(f4 + (size_t)ni[6] * 32 + lane);
            v2 = ldcg4(f4 + (size_t)ni[7] * 32 + lane);
            v3 = ldcg4(f4 + (size_t)ni[8] * 32 + lane);
            v4 = ldcg4(f4 + (size_t)ni[9] * 32 + lane);
            s.x += v0.x + v1.x + v2.x + v3.x + v4.x;
            s.y += v0.y + v1.y + v2.y + v3.y + v4.y;
            s.z += v0.z + v1.z + v2.z + v3.z + v4.z;
            s.w += v0.w + v1.w + v2.w + v3.w + v4.w;
            s.x *= 0.1f; s.y *= 0.1f; s.z *= 0.1f; s.w *= 0.1f;

            const int r = rbase + i;
            const uint32_t oS = (uint32_t)r * (A_STRIDE * 2) + lane * 8;  // k = lane*4
            const uint32_t oM = oS + 256;                                 // k = 128+lane*4
            *(uint2*)(sm + SM_AHI + oS) = make_uint2(pack_hi2(vs.x, vs.y), pack_hi2(vs.z, vs.w));
            *(uint2*)(sm + SM_ALO + oS) = make_uint2(pack_hi2(bf_res(vs.x), bf_res(vs.y)),
                                                     pack_hi2(bf_res(vs.z), bf_res(vs.w)));
            *(uint2*)(sm + SM_AHI + oM) = make_uint2(pack_hi2(s.x, s.y), pack_hi2(s.z, s.w));
            *(uint2*)(sm + SM_ALO + oM) = make_uint2(pack_hi2(bf_res(s.x), bf_res(s.y)),
                                                     pack_hi2(bf_res(s.z), bf_res(s.w)));
        }
    }
    __syncthreads();   // the only CTA barrier

    // ---------- MMA: warp tile m32 x n32, 16 k-steps, W prefetch depth 2 ----------
    const int n0w = wid * 4;   // col-block base (8-col units)
    const uint4* wbase = &g_wfrag[n0w * 32 + lane];   // + ks*512 + j*32

    float acc0[4][4], acc1[4][4];
    #pragma unroll
    for (int j = 0; j < 4; ++j)
        #pragma unroll
        for (int c = 0; c < 4; ++c) { acc0[j][c] = 0.f; acc1[j][c] = 0.f; }

    const uint32_t aAddr0 = (uint32_t)(((lane & 15)) * A_STRIDE + (lane >> 4) * 8) * 2;
    const uint32_t aAddr1 = aAddr0 + 16 * A_STRIDE * 2;

    uint4 fA[4], fB[4];
    #pragma unroll
    for (int j = 0; j < 4; ++j) fA[j] = ldcg4u(wbase + 0 * 512 + j * 32);
    #pragma unroll
    for (int j = 0; j < 4; ++j) fB[j] = ldcg4u(wbase + 1 * 512 + j * 32);

    #pragma unroll 4
    for (int ks = 0; ks < 16; ++ks) {
        uint32_t aHi0[4], aLo0[4], aHi1[4], aLo1[4];
        const uint32_t ao = (uint32_t)(ks * 16) * 2;
        ldsm_x4(aHi0, smb + SM_AHI + aAddr0 + ao);
        ldsm_x4(aLo0, smb + SM_ALO + aAddr0 + ao);
        ldsm_x4(aHi1, smb + SM_AHI + aAddr1 + ao);
        ldsm_x4(aLo1, smb + SM_ALO + aAddr1 + ao);

        uint4* fc = (ks & 1) ? fB : fA;
        #pragma unroll
        for (int j = 0; j < 4; ++j) {
            uint4 f = fc[j];
            mma_bf16(acc0[j], aHi0, f.x, f.y);
            mma_bf16(acc0[j], aHi0, f.z, f.w);
            mma_bf16(acc0[j], aLo0, f.x, f.y);
            mma_bf16(acc1[j], aHi1, f.x, f.y);
            mma_bf16(acc1[j], aHi1, f.z, f.w);
            mma_bf16(acc1[j], aLo1, f.x, f.y);
        }
        // refill the buffer just consumed with kstep ks+2 ((ks+2)&15 wraps
        // harmlessly for the last two iterations)
        const int kn = (ks + 2) & 15;
        #pragma unroll
        for (int j = 0; j < 4; ++j) fc[j] = ldcg4u(wbase + kn * 512 + j * 32);
    }

    // ---------- epilogue: relu + float2 stores, both m-halves ----------
    #pragma unroll
    for (int h = 0; h < 2; ++h) {
        float (*acc)[4] = h ? acc1 : acc0;
        const int r0 = rowBase + h * 16 + (lane >> 2);
        const int r1 = r0 + 8;
        const int c0 = wid * 32 + (lane & 3) * 2;
        #pragma unroll
        for (int j = 0; j < 4; ++j) {
            const int col = c0 + j * 8;
            if (r0 < Bn) {
                float2 o;
                o.x = fmaxf(acc[j][0], 0.f);
                o.y = fmaxf(acc[j][1], 0.f);
                *(float2*)&out[(size_t)r0 * H_DIM + col] = o;
            }
            if (r1 < Bn) {
                float2 o;
                o.x = fmaxf(acc[j][2], 0.f);
                o.y = fmaxf(acc[j][3], 0.f);
                *(float2*)&out[(size_t)r1 * H_DIM + col] = o;
            }
        }
    }
}

extern "C" void kernel_launch(void* const* d_in, const int* in_sizes, int n_in,
                              void* d_out, int out_size)
{
    const int*   nodes  = (const int*)d_in[0];
    const int*   neigh  = (const int*)d_in[1];
    const float* feat   = (const float*)d_in[2];
    const float* weight = (const float*)d_in[3];
    float*       out    = (float*)d_out;
    const int Bn = in_sizes[0];

    wfrag_kernel<<<64, 128>>>(weight);

    const int grid = (Bn + TILE_M - 1) / TILE_M;
    sage_main_kernel<<<grid, NTHREADS>>>(nodes, neigh, feat, out, Bn);
}